// round 17
// baseline (speedup 1.0000x reference)
#include <cuda_runtime.h>
#include <cuda_fp16.h>
#include <cstdint>
#include <math.h>

// Single fused kernel, barrier-free mainloop, single k-step MMA,
// column-permuted B fragments -> dense STG.128 epilogue.
// CTA: 128 rows x 512 cols, 8 warps = 4 row groups (32r) x 2 col groups (256c).
// A and B features both fp16: dot = ah.bh, rel_err ~4e-4 (budget 1e-3).
// Column permutation within each 16-col tile: global col w <-> (nt,n) with
//   nt=(w>>1)&1, n=((w>>2)<<1)|(w&1), so lane L's accumulator quad
//   (nt0.c0, nt0.c1, nt1.c0, nt1.c1) = cols ct*16+(L&3)*4+{0,1,2,3} -> STG.128.

#define SM_A  0            // 2 groups x 128 rows x 48B = 12288
#define SM_B  12288        // 32 ct x 2 g x 32 lanes x 16B = 32768
#define SM_TOT 45056       // static smem (< 48KB)

__device__ __forceinline__ uint32_t smem_u32(const void* p) {
    uint32_t a;
    asm("{ .reg .u64 t; cvta.to.shared.u64 t, %1; cvt.u32.u64 %0, t; }" : "=r"(a) : "l"(p));
    return a;
}
__device__ __forceinline__ void ldm_x4(uint32_t* r, uint32_t addr) {
    asm volatile("ldmatrix.sync.aligned.m8n8.x4.shared.b16 {%0,%1,%2,%3}, [%4];"
                 : "=r"(r[0]), "=r"(r[1]), "=r"(r[2]), "=r"(r[3]) : "r"(addr));
}
__device__ __forceinline__ void mma16816(float* d, const uint32_t* a,
                                         uint32_t b0, uint32_t b1) {
    asm volatile(
        "mma.sync.aligned.m16n8k16.row.col.f32.f16.f16.f32 "
        "{%0,%1,%2,%3}, {%4,%5,%6,%7}, {%8,%9}, {%0,%1,%2,%3};"
        : "+f"(d[0]), "+f"(d[1]), "+f"(d[2]), "+f"(d[3])
        : "r"(a[0]), "r"(a[1]), "r"(a[2]), "r"(a[3]), "r"(b0), "r"(b1));
}
__device__ __forceinline__ unsigned long long pack4h(float f0, float f1,
                                                     float f2, float f3) {
    __half2 lo = __floats2half2_rn(f0, f1);
    __half2 hi = __floats2half2_rn(f2, f3);
    unsigned long long r;
    asm("mov.b64 %0, {%1, %2};" : "=l"(r)
        : "r"(*(unsigned int*)&lo), "r"(*(unsigned int*)&hi));
    return r;
}

__global__ void __launch_bounds__(256, 2)
qk_one(const float* __restrict__ x, const float* __restrict__ c,
       float* __restrict__ out, int C) {
    __shared__ __align__(16) unsigned char sm[SM_TOT];
    const int tid = threadIdx.x, wid = tid >> 5, lane = tid & 31;
    const int row0 = blockIdx.y * 128, col0 = blockIdx.x * 512;
    const uint32_t sb = smem_u32(sm);

    // ---------------- Prologue ----------------
    // A features: tids 0-127, one row each, fp16, stride 48.
    if (tid < 128) {
        const float* src = x + (size_t)(row0 + tid) * 8;
        float cv[8], sv[8];
        #pragma unroll
        for (int j = 0; j < 8; j++) sincosf(0.5f * src[j], &sv[j], &cv[j]);
        float pf[4][4];
        #pragma unroll
        for (int p = 0; p < 4; p++) {
            pf[p][0] = cv[2*p] * cv[2*p+1];
            pf[p][1] = cv[2*p] * sv[2*p+1];
            pf[p][2] = sv[2*p] * cv[2*p+1];
            pf[p][3] = sv[2*p] * sv[2*p+1];
        }
        #pragma unroll
        for (int g = 0; g < 2; g++) {
            __align__(16) __half v[16];
            #pragma unroll
            for (int a = 0; a < 4; a++)
                #pragma unroll
                for (int b = 0; b < 4; b++)
                    v[a*4+b] = __float2half_rn(pf[2*g][a] * pf[2*g+1][b]);
            uint4* dst = (uint4*)(sm + SM_A + g * 6144 + tid * 48);
            dst[0] = ((const uint4*)v)[0];
            dst[1] = ((const uint4*)v)[1];
        }
    }

    // B fragments: 1024 (col,g) units, 4 per thread, fragment order with
    // the column permutation nt=(w>>1)&1, n=((w>>2)<<1)|(w&1).
    #pragma unroll
    for (int p = 0; p < 4; p++) {
        const int u = tid + p * 256;        // 0..1023
        const int col = u & 511, g = u >> 9;
        float4 cv4 = *(const float4*)(c + (size_t)(col0 + col) * 8 + g * 4);
        float cw[4], sw[4];
        sincosf(0.5f * cv4.x, &sw[0], &cw[0]);
        sincosf(0.5f * cv4.y, &sw[1], &cw[1]);
        sincosf(0.5f * cv4.z, &sw[2], &cw[2]);
        sincosf(0.5f * cv4.w, &sw[3], &cw[3]);
        float pa[4] = {cw[0]*cw[1], cw[0]*sw[1], sw[0]*cw[1], sw[0]*sw[1]};
        float pb[4] = {cw[2]*cw[3], cw[2]*sw[3], sw[2]*cw[3], sw[2]*sw[3]};

        const int ct = col >> 4, w = col & 15;
        const int nt = (w >> 1) & 1;                    // permuted tile-half
        const int nrow = ((w >> 2) << 1) | (w & 1);     // permuted n index
        unsigned char* base = sm + SM_B + ((ct * 2 + g) * 32) * 16 + nt * 8;
        #pragma unroll
        for (int j = 0; j < 4; j++) {
            int k0 = 2 * j, k1 = 2 * j + 1, k8 = 2 * j + 8, k9 = 2 * j + 9;
            unsigned long long v = pack4h(
                pa[k0 >> 2] * pb[k0 & 3], pa[k1 >> 2] * pb[k1 & 3],
                pa[k8 >> 2] * pb[k8 & 3], pa[k9 >> 2] * pb[k9 & 3]);
            *(unsigned long long*)(base + (nrow * 4 + j) * 16) = v;
        }
    }
    __syncthreads();    // the ONLY barrier

    // ---------------- Persistent a-frags ----------------
    const int wr = wid & 3;       // row group
    const int wc = wid >> 2;      // col group
    uint32_t af[2][2][4];         // [g][mt][4], 16 regs
    {
        const uint32_t aoff =
            (uint32_t)(wr * 32 + (lane & 15)) * 48 + (lane >> 4) * 16;
        #pragma unroll
        for (int mt = 0; mt < 2; mt++) {
            ldm_x4(af[0][mt], sb + SM_A + aoff + mt * 16 * 48);
            ldm_x4(af[1][mt], sb + SM_A + 6144 + aoff + mt * 16 * 48);
        }
    }

    const size_t rbase = (size_t)(row0 + wr * 32 + (lane >> 2));
    const uint32_t bbase = sb + SM_B + lane * 16;

    #pragma unroll 4
    for (int i = 0; i < 16; i++) {
        const int ct = wc * 16 + i;           // CTA-local 16-col step
        uint4 cur0, cur1;
        {
            const uint32_t a0 = bbase + (uint32_t)(ct * 2 + 0) * 512;
            const uint32_t a1 = bbase + (uint32_t)(ct * 2 + 1) * 512;
            asm volatile("ld.shared.v4.b32 {%0,%1,%2,%3}, [%4];"
                         : "=r"(cur0.x), "=r"(cur0.y), "=r"(cur0.z), "=r"(cur0.w)
                         : "r"(a0));
            asm volatile("ld.shared.v4.b32 {%0,%1,%2,%3}, [%4];"
                         : "=r"(cur1.x), "=r"(cur1.y), "=r"(cur1.z), "=r"(cur1.w)
                         : "r"(a1));
        }

        float acc[2][2][2][4] = {};   // [g][mt][nt][4]
        // Single k-step: 8 independent MMAs.
        #pragma unroll
        for (int mt = 0; mt < 2; mt++) {
            mma16816(acc[0][mt][0], af[0][mt], cur0.x, cur0.y);
            mma16816(acc[1][mt][0], af[1][mt], cur1.x, cur1.y);
            mma16816(acc[0][mt][1], af[0][mt], cur0.z, cur0.w);
            mma16816(acc[1][mt][1], af[1][mt], cur1.z, cur1.w);
        }

        // Epilogue: lane quad = 4 consecutive cols -> STG.128.
        const int cbase = col0 + ct * 16 + (lane & 3) * 4;
        #pragma unroll
        for (int mt = 0; mt < 2; mt++) {
            size_t rm = rbase + mt * 16;
            float4 v;
            v.x = fabsf(acc[0][mt][0][0] * acc[1][mt][0][0]);
            v.y = fabsf(acc[0][mt][0][1] * acc[1][mt][0][1]);
            v.z = fabsf(acc[0][mt][1][0] * acc[1][mt][1][0]);
            v.w = fabsf(acc[0][mt][1][1] * acc[1][mt][1][1]);
            *(float4*)(out + rm * C + cbase) = v;
            v.x = fabsf(acc[0][mt][0][2] * acc[1][mt][0][2]);
            v.y = fabsf(acc[0][mt][0][3] * acc[1][mt][0][3]);
            v.z = fabsf(acc[0][mt][1][2] * acc[1][mt][1][2]);
            v.w = fabsf(acc[0][mt][1][3] * acc[1][mt][1][3]);
            *(float4*)(out + (rm + 8) * C + cbase) = v;
        }
    }
}

extern "C" void kernel_launch(void* const* d_in, const int* in_sizes, int n_in,
                              void* d_out, int out_size) {
    const float* x = (const float*)d_in[0];
    const float* c = (const float*)d_in[1];
    float* out = (float*)d_out;

    int B = in_sizes[0] / 8;   // 8192
    int C = in_sizes[1] / 8;   // 2048

    dim3 grid(C / 512, B / 128);   // (4, 64) = 256 CTAs
    qk_one<<<grid, 256>>>(x, c, out, C);
}